// round 13
// baseline (speedup 1.0000x reference)
#include <cuda_runtime.h>
#include <cstdint>

#define Bn 128
#define Ln 256
#define Dn 512
#define Hn 1024
#define BH (Bn*Hn)      // 131072
#define KSPLIT 8
#define NCTA 128

// Does this compilation pass allow arch-specific (tcgen05) instructions?
#if defined(__CUDA_ARCH_FEAT_SM103_ALL) || defined(__CUDA_ARCH_FEAT_SM100_ALL) || \
    (defined(__CUDA_ARCH_FAMILY_SPECIFIC__) && (__CUDA_ARCH_FAMILY_SPECIFIC__ == 1000 || __CUDA_ARCH_FAMILY_SPECIFIC__ == 1030))
#define HAS_TCGEN05 1
#else
#define HAS_TCGEN05 0
#endif

// scratch (device globals: no allocations allowed)
__device__ float g_xp[(size_t)Ln*BH];   // (L,B,H) pre-activations x@Wx + bx + bh
__device__ float g_hs[(size_t)Ln*BH];   // hidden states per step (for k_out)
__device__ float g_hi[BH];              // h tf32-hi, MMA-ready swizzled blocked layout
__device__ float g_lo[BH];              // h residual lo, same layout (tc path)
__device__ float g_h[2][BH];            // ping-pong h (ffma fallback path)
__device__ float g_zp[KSPLIT][BH];      // K-split partial sums of h@Wh
__device__ float g_xhi[(size_t)32768*Dn];  // x' tf32-hi blocked [mt][ac][b][k]
__device__ float g_xlo[(size_t)32768*Dn];  // x' residual lo, same layout
__device__ float g_wxhi[(size_t)Dn*Hn];    // Wx^T tf32-hi blocked [nt][ac][n][k]
__device__ float g_wxlo[(size_t)Dn*Hn];    // Wx^T residual lo
__device__ unsigned g_cnt[8][128];      // 8 arrive counters, 512B apart
__device__ unsigned g_phase;            // barrier generation (monotonic)

// ---------- packed f32x2 helpers ----------
__device__ __forceinline__ unsigned long long pk2(float lo, float hi) {
    unsigned long long r;
    asm("mov.b64 %0, {%1,%2};" : "=l"(r) : "f"(lo), "f"(hi));
    return r;
}
__device__ __forceinline__ void upk2(unsigned long long v, float& lo, float& hi) {
    asm("mov.b64 {%0,%1}, %2;" : "=f"(lo), "=f"(hi) : "l"(v));
}
__device__ __forceinline__ unsigned long long ffma2(unsigned long long a,
                                                    unsigned long long b,
                                                    unsigned long long c) {
    unsigned long long d;
    asm("fma.rn.f32x2 %0, %1, %2, %3;" : "=l"(d) : "l"(a), "l"(b), "l"(c));
    return d;
}

// ---------- low-contention grid barrier (replay-safe) ----------
__device__ __forceinline__ void grid_sync() {
    __syncthreads();
    if (threadIdx.x == 0) {
        unsigned ph = *(volatile unsigned*)&g_phase;
        __threadfence();
        atomicAdd(&g_cnt[blockIdx.x & 7][0], 1);
        if (blockIdx.x == 0) {
            unsigned sum;
            do {
                sum = 0;
#pragma unroll
                for (int i = 0; i < 8; i++) sum += *(volatile unsigned*)&g_cnt[i][0];
            } while (sum < NCTA);
#pragma unroll
            for (int i = 0; i < 8; i++) *(volatile unsigned*)&g_cnt[i][0] = 0;
            __threadfence();
            *(volatile unsigned*)&g_phase = ph + 1;
        } else {
            while (*(volatile unsigned*)&g_phase == ph) { __nanosleep(32); }
        }
        __threadfence();
    }
    __syncthreads();
}

// ---------- activation ----------
__device__ __forceinline__ float act1(float z, float& c) {
    float sg = 1.0f / (1.0f + __expf(-z));
    float g = tanhf(z);
    c = sg * (c + g);
    return sg * tanhf(c);
}

__device__ __forceinline__ float tf32_hi_f(float x) {
    float r;
    asm("cvt.rna.tf32.f32 %0, %1;" : "=f"(r) : "f"(x));   // plain PTX, sm_80+
    return r;
}

#if HAS_TCGEN05
// ================= tcgen05 helpers (only in arch-specific pass) =================
__device__ __forceinline__ uint32_t smem_u32(const void* p) {
    uint32_t a;
    asm("{ .reg .u64 t; cvta.to.shared.u64 t, %1; cvt.u32.u64 %0, t; }" : "=r"(a) : "l"(p));
    return a;
}
__device__ __forceinline__ uint32_t elect_one() {
    uint32_t p;
    asm volatile("{ .reg .pred p; elect.sync _|p, 0xFFFFFFFF; selp.b32 %0, 1, 0, p; }" : "=r"(p));
    return p;
}
__device__ __forceinline__ void mma_tf32_ss(uint32_t d_tmem, uint64_t a_desc,
                                            uint64_t b_desc, uint32_t idesc, bool acc) {
    uint32_t en = acc ? 1u : 0u;
    asm volatile(
        "{\n\t.reg .pred p;\n\t"
        "setp.ne.u32 p, %4, 0;\n\t"
        "tcgen05.mma.cta_group::1.kind::tf32 [%0], %1, %2, %3, {%5, %5, %5, %5}, p;\n\t}"
        :: "r"(d_tmem), "l"(a_desc), "l"(b_desc), "r"(idesc), "r"(en), "r"(0u)
        : "memory");
}
__device__ __forceinline__ void bulk_g2s(uint32_t dst, const void* src,
                                         uint32_t bytes, uint32_t mbar) {
    asm volatile(
        "cp.async.bulk.shared::cta.global.mbarrier::complete_tx::bytes [%0], [%1], %2, [%3];"
        :: "r"(dst), "l"(src), "r"(bytes), "r"(mbar) : "memory");
}
#define MBAR_INIT(a, c) asm volatile("mbarrier.init.shared.b64 [%0], %1;" :: "r"(a), "r"(c) : "memory")
#define MBAR_EXPECT_TX(a, b) asm volatile("mbarrier.arrive.expect_tx.shared.b64 _, [%0], %1;" :: "r"(a), "r"(b) : "memory")
#define MBAR_WAIT(a, par) do { \
    asm volatile("{\n\t.reg .pred P1;\n\tWL_%=:\n\t" \
        "mbarrier.try_wait.parity.acquire.cta.shared::cta.b64 P1, [%0], %1, 0x989680;\n\t" \
        "@P1 bra.uni WD_%=;\n\tbra.uni WL_%=;\n\tWD_%=:\n\t}" \
        :: "r"(a), "r"(par) : "memory"); } while (0)
#define TC_ALLOC(sm, n)  asm volatile("tcgen05.alloc.cta_group::1.sync.aligned.shared::cta.b32 [%0], %1;" :: "r"(sm), "r"(n) : "memory")
#define TC_DEALLOC(t, n) asm volatile("tcgen05.dealloc.cta_group::1.sync.aligned.b32 %0, %1;" :: "r"(t), "r"(n))
#define TC_COMMIT(mb)    asm volatile("tcgen05.commit.cta_group::1.mbarrier::arrive::one.shared::cluster.b64 [%0];" :: "r"(mb) : "memory")
#define TC_FENCE_AFTER() asm volatile("tcgen05.fence::after_thread_sync;" ::: "memory")
#define TC_FENCE_BEFORE() asm volatile("tcgen05.fence::before_thread_sync;" ::: "memory")
#define TC_WAIT_LD()     asm volatile("tcgen05.wait::ld.sync.aligned;" ::: "memory")
#define FENCE_ASYNC_SHARED() asm volatile("fence.proxy.async.shared::cta;" ::: "memory")

#define LDTM_X32(r, addr) \
    asm volatile("tcgen05.ld.sync.aligned.32x32b.x32.b32 " \
        "{%0,%1,%2,%3,%4,%5,%6,%7,%8,%9,%10,%11,%12,%13,%14,%15," \
        "%16,%17,%18,%19,%20,%21,%22,%23,%24,%25,%26,%27,%28,%29,%30,%31}, [%32];" \
        : "=r"((r)[0]), "=r"((r)[1]), "=r"((r)[2]), "=r"((r)[3]), \
          "=r"((r)[4]), "=r"((r)[5]), "=r"((r)[6]), "=r"((r)[7]), \
          "=r"((r)[8]), "=r"((r)[9]), "=r"((r)[10]), "=r"((r)[11]), \
          "=r"((r)[12]), "=r"((r)[13]), "=r"((r)[14]), "=r"((r)[15]), \
          "=r"((r)[16]), "=r"((r)[17]), "=r"((r)[18]), "=r"((r)[19]), \
          "=r"((r)[20]), "=r"((r)[21]), "=r"((r)[22]), "=r"((r)[23]), \
          "=r"((r)[24]), "=r"((r)[25]), "=r"((r)[26]), "=r"((r)[27]), \
          "=r"((r)[28]), "=r"((r)[29]), "=r"((r)[30]), "=r"((r)[31]) \
        : "r"(addr))

static __device__ __forceinline__ uint64_t make_desc(uint32_t addr) {
    uint64_t d = ((uint64_t)2 << 61) | ((uint64_t)1 << 46) |
                 ((uint64_t)64 << 32) | ((uint64_t)1 << 16);
    return d | ((uint64_t)(addr >> 4) & 0x3FFF);
}
#define IDESC_TF32 ((1u<<4) | (2u<<7) | (2u<<10) | ((64u/8)<<17) | ((128u/16)<<24))
#endif  // HAS_TCGEN05

// SMEM layout for scan tc path (dynamic)
#define SM_TMEMPTR 0
#define SM_CPMBAR  8
#define SM_MMAMBAR 16
#define SM_AHI     1024
#define SM_ALO     (SM_AHI + 65536)
#define SM_BHI     (SM_ALO + 65536)
#define SM_BLO     (SM_BHI + 32768)
#define SM_TOTAL   (SM_BLO + 32768)       // 197632 bytes

// SMEM layout for xp tc kernel
#define XP_TMEMPTR 0
#define XP_MBA0    8
#define XP_MBA1    16
#define XP_MBB0    24
#define XP_MBB1    32
#define XP_MBB2    40
#define XP_MBM0    48
#define XP_MBM1    56
#define XP_A       1024                    // 2 slots x 65536 (hi at +0, lo at +32768)
#define XP_B       (XP_A + 131072)         // 3 slots x 32768 (hi at +0, lo at +16384)
#define XP_SMEM    (XP_B + 98304)          // 230400 bytes

// ---------- conversion: x -> tf32 hi/lo in MMA-ready blocked layout ----------
// g_xhi byte addr = mt*262144 + (k>>5)*16384 + swz(b*128 + (k&31)*4); mt = l
__global__ void __launch_bounds__(256) k_cvt_x(const float* __restrict__ x) {
#if !HAS_TCGEN05
    return;   // fallback image computes xp directly from x
#else
    const int mt = blockIdx.x;             // = l
    char* dhi = (char*)g_xhi + (size_t)mt * 262144;
    char* dlo = (char*)g_xlo + (size_t)mt * 262144;
    for (int idx = threadIdx.x; idx < 128 * 128; idx += 256) {   // (b, k4)
        int b = idx >> 7, k4 = idx & 127;
        float4 v = *(const float4*)(x + ((size_t)b * Ln + mt) * Dn + k4 * 4);
        float4 hi4, lo4;
        hi4.x = tf32_hi_f(v.x); lo4.x = v.x - hi4.x;
        hi4.y = tf32_hi_f(v.y); lo4.y = v.y - hi4.y;
        hi4.z = tf32_hi_f(v.z); lo4.z = v.z - hi4.z;
        hi4.w = tf32_hi_f(v.w); lo4.w = v.w - hi4.w;
        int k = k4 * 4;
        uint32_t off = (uint32_t)(b * 128 + (k & 31) * 4);
        uint32_t sw = off ^ ((off >> 3) & 0x70);
        uint32_t full = (uint32_t)((k >> 5) * 16384) + sw;
        *(float4*)(dhi + full) = hi4;
        *(float4*)(dlo + full) = lo4;
    }
#endif
}

// ---------- conversion: Wx^T -> tf32 hi/lo blocked [nt][ac][n][k] ----------
// byte addr = nt*131072 + (k>>5)*8192 + swz(n*128 + (k&31)*4)
__global__ void __launch_bounds__(256) k_cvt_w(const float* __restrict__ Wx) {
#if !HAS_TCGEN05
    return;
#else
    const int nt = blockIdx.x;             // 0..15
    char* dhi = (char*)g_wxhi + (size_t)nt * 131072;
    char* dlo = (char*)g_wxlo + (size_t)nt * 131072;
    for (int idx = threadIdx.x; idx < 512 * 16; idx += 256) {    // (k, n4)
        int k = idx >> 4, n4 = idx & 15;
        float4 v = *(const float4*)(Wx + (size_t)k * Hn + nt * 64 + n4 * 4);
        float w[4] = {v.x, v.y, v.z, v.w};
#pragma unroll
        for (int j = 0; j < 4; j++) {
            int n = n4 * 4 + j;
            float hi = tf32_hi_f(w[j]);
            uint32_t off = (uint32_t)(n * 128 + (k & 31) * 4);
            uint32_t sw = off ^ ((off >> 3) & 0x70);
            uint32_t full = (uint32_t)((k >> 5) * 8192) + sw;
            *(float*)(dhi + full) = hi;
            *(float*)(dlo + full) = w[j] - hi;
        }
    }
#endif
}

// ---------- xp GEMM: tcgen05 3xTF32 (feature image) / FFMA tiles (fallback) ----------
// grid (2 n-halves, 256 m-tiles). Feature: D[128m,512n] in TMEM, K=512 streamed.
__global__ void __launch_bounds__(256, 1) k_xp_tc(const float* __restrict__ x,
                                                  const float* __restrict__ Wx,
                                                  const float* __restrict__ bx,
                                                  const float* __restrict__ bh) {
    extern __shared__ char smem[];
    const int tid = threadIdx.x;
#if HAS_TCGEN05
    const uint32_t smb = smem_u32(smem);
    const int wid = tid >> 5, lid = tid & 31;
    const int nh = blockIdx.x;             // 0..1
    const int mt = blockIdx.y;             // 0..255

    if (tid == 0) {
        MBAR_INIT(smb + XP_MBA0, 1);
        MBAR_INIT(smb + XP_MBA1, 1);
        MBAR_INIT(smb + XP_MBB0, 1);
        MBAR_INIT(smb + XP_MBB1, 1);
        MBAR_INIT(smb + XP_MBB2, 1);
        MBAR_INIT(smb + XP_MBM0, 1);
        MBAR_INIT(smb + XP_MBM1, 1);
    }
    if (wid == 0) TC_ALLOC(smb + XP_TMEMPTR, 512);
    __syncthreads();
    uint32_t tmem;
    asm volatile("ld.shared.b32 %0, [%1];" : "=r"(tmem) : "r"(smb + XP_TMEMPTR));

    if (tid == 0) {
        const char* xhi = (const char*)g_xhi + (size_t)mt * 262144;
        const char* xlo = (const char*)g_xlo + (size_t)mt * 262144;
        const char* whi = (const char*)g_wxhi;
        const char* wlo = (const char*)g_wxlo;
        const uint32_t amb[2] = {smb + XP_MBA0, smb + XP_MBA1};
        const uint32_t bmb[3] = {smb + XP_MBB0, smb + XP_MBB1, smb + XP_MBB2};
        const uint32_t mbM[2] = {smb + XP_MBM0, smb + XP_MBM1};

        // prologue: A chunk kc=0 -> slot 0; B for it=0,1 -> slots 0,1
        MBAR_EXPECT_TX(amb[0], 65536u);
        bulk_g2s(smb + XP_A, xhi, 32768u, amb[0]);
        bulk_g2s(smb + XP_A + 32768, xlo, 32768u, amb[0]);
#pragma unroll
        for (int p = 0; p < 2; p++) {      // it=p: kc=0, nt=p
            size_t bsrc = (size_t)(nh * 8 + p) * 131072;   // + kc*16384 (kc=0)
            MBAR_EXPECT_TX(bmb[p], 32768u);
            bulk_g2s(smb + XP_B + p * 32768, whi + bsrc, 16384u, bmb[p]);
            bulk_g2s(smb + XP_B + p * 32768 + 16384, wlo + bsrc, 16384u, bmb[p]);
        }

        for (int it = 0; it < 64; it++) {
            const int kc = it >> 3, nt = it & 7;
            if (nt == 0) MBAR_WAIT(amb[kc & 1], (kc >> 1) & 1);
            MBAR_WAIT(bmb[it % 3], (it / 3) & 1);

            const uint32_t aBase = smb + XP_A + (kc & 1) * 65536;
            const uint32_t bBase = smb + XP_B + (it % 3) * 32768;
#pragma unroll
            for (int pass = 0; pass < 3; pass++) {
                uint64_t ad = make_desc(aBase + ((pass == 2) ? 32768u : 0u));
                uint64_t bd = make_desc(bBase + ((pass == 1) ? 16384u : 0u));
#pragma unroll
                for (int s = 0; s < 8; s++) {
                    uint64_t ao = (uint64_t)((s >> 2) * 1024 + (s & 3) * 2);
                    uint64_t bo = (uint64_t)((s >> 2) * 512 + (s & 3) * 2);
                    // zero-init each nt's accumulator at its FIRST MMA (kc==0)
                    mma_tf32_ss(tmem + nt * 64, ad + ao, bd + bo, IDESC_TF32,
                                !(kc == 0 && pass == 0 && s == 0));
                }
            }
            // commit it -> mbM[it&1]; wait commit it-1 on its own barrier with
            // EXACT per-barrier phase (each barrier completes once per 2 its).
            TC_COMMIT(mbM[it & 1]);
            if (it >= 1) MBAR_WAIT(mbM[(it - 1) & 1], ((it - 1) >> 1) & 1);

            if (it + 2 < 64) {            // load B for it+2 (its old user = it-1, waited)
                const int jt = it + 2;
                const int slot = jt % 3;
                size_t bsrc = (size_t)(nh * 8 + (jt & 7)) * 131072 + (size_t)(jt >> 3) * 16384;
                MBAR_EXPECT_TX(bmb[slot], 32768u);
                bulk_g2s(smb + XP_B + slot * 32768, whi + bsrc, 16384u, bmb[slot]);
                bulk_g2s(smb + XP_B + slot * 32768 + 16384, wlo + bsrc, 16384u, bmb[slot]);
            }
            if (nt == 6 && kc < 7) {      // load A for kc+1 (old user kc-1 long done)
                const int nk = kc + 1;
                MBAR_EXPECT_TX(amb[nk & 1], 65536u);
                bulk_g2s(smb + XP_A + (nk & 1) * 65536, xhi + nk * 32768, 32768u, amb[nk & 1]);
                bulk_g2s(smb + XP_A + (nk & 1) * 65536 + 32768, xlo + nk * 32768, 32768u, amb[nk & 1]);
            }
        }
        MBAR_WAIT(mbM[1], 1);             // commit 63: barrier1 use #31 -> phase parity 1
    }
    __syncthreads();
    TC_FENCE_AFTER();

    // epilogue: read D per n-tile, add bias, store to g_xp
    {
        const int m = (wid & 3) * 32 + lid;
        const int row = blockIdx.y * 128 + m;
        for (int nt = 0; nt < 8; nt++) {
            uint32_t r[32];
            const int cb = (wid < 4) ? 0 : 32;
            LDTM_X32(r, tmem + nt * 64 + cb);
            TC_WAIT_LD();
            const int n0 = (nh * 8 + nt) * 64 + cb;
            float* dst = g_xp + (size_t)row * Hn + n0;
#pragma unroll
            for (int q = 0; q < 8; q++) {
                float4 bxv = *(const float4*)(bx + n0 + 4 * q);
                float4 bhv = *(const float4*)(bh + n0 + 4 * q);
                float4 v;
                v.x = __uint_as_float(r[4 * q + 0]) + bxv.x + bhv.x;
                v.y = __uint_as_float(r[4 * q + 1]) + bxv.y + bhv.y;
                v.z = __uint_as_float(r[4 * q + 2]) + bxv.z + bhv.z;
                v.w = __uint_as_float(r[4 * q + 3]) + bxv.w + bhv.w;
                *(float4*)(dst + 4 * q) = v;
            }
        }
    }
    TC_FENCE_BEFORE();
    __syncthreads();
    if (wid == 0) TC_DEALLOC(tmem, 512);

#else
    // ---------- FFMA fallback: 4 of the old 128x128 tiles per CTA ----------
    float (*As)[132] = (float(*)[132])smem;                 // 16 x 132
    float (*Bs)[128] = (float(*)[128])(smem + 16 * 132 * 4);

    const int ty = tid >> 4, tx = tid & 15;
    const int m0 = ty * 8, n0 = tx * 8;
    const int mb = blockIdx.y;

    for (int nb4 = 0; nb4 < 4; nb4++) {
        const int nb = blockIdx.x * 4 + nb4;
        unsigned long long acc[8][4];
#pragma unroll
        for (int i = 0; i < 8; i++)
#pragma unroll
            for (int j = 0; j < 4; j++) acc[i][j] = 0ULL;

        for (int kt = 0; kt < Dn / 16; kt++) {
            const int kb = kt * 16;
#pragma unroll
            for (int p = 0; p < 2; p++) {
                int s = tid + p * 256;
                int row = s >> 2, kq = s & 3;
                int gm = mb * 128 + row;
                int bidx = gm & 127, lidx = gm >> 7;
                float4 v = *(const float4*)(x + ((size_t)bidx * Ln + lidx) * Dn + kb + kq * 4);
                As[kq * 4 + 0][row] = v.x;
                As[kq * 4 + 1][row] = v.y;
                As[kq * 4 + 2][row] = v.z;
                As[kq * 4 + 3][row] = v.w;
            }
#pragma unroll
            for (int p = 0; p < 2; p++) {
                int s = tid + p * 256;
                int kr = s >> 5, c4 = s & 31;
                *(float4*)&Bs[kr][c4 * 4] =
                    *(const float4*)(Wx + (size_t)(kb + kr) * Hn + nb * 128 + c4 * 4);
            }
            __syncthreads();
#pragma unroll
            for (int k = 0; k < 16; k++) {
                float a[8];
                *(float4*)&a[0] = *(const float4*)&As[k][m0];
                *(float4*)&a[4] = *(const float4*)&As[k][m0 + 4];
                const unsigned long long* bsrc = (const unsigned long long*)&Bs[k][n0];
                unsigned long long b2[4];
#pragma unroll
                for (int j = 0; j < 4; j++) b2[j] = bsrc[j];
#pragma unroll
                for (int i = 0; i < 8; i++) {
                    unsigned long long a2 = pk2(a[i], a[i]);
#pragma unroll
                    for (int j = 0; j < 4; j++) acc[i][j] = ffma2(a2, b2[j], acc[i][j]);
                }
            }
            __syncthreads();
        }

        float bb[8];
#pragma unroll
        for (int j = 0; j < 8; j++) {
            int gn = nb * 128 + n0 + j;
            bb[j] = bx[gn] + bh[gn];
        }
#pragma unroll
        for (int i = 0; i < 8; i++) {
            int gm = mb * 128 + m0 + i;
            float* orow = g_xp + (size_t)gm * Hn + nb * 128 + n0;
#pragma unroll
            for (int j = 0; j < 4; j++) {
                float lo, hi;
                upk2(acc[i][j], lo, hi);
                *(float2*)(orow + 2 * j) = make_float2(lo + bb[2 * j], hi + bb[2 * j + 1]);
            }
        }
        __syncthreads();
    }
#endif
}

// ---------- persistent fused scan: tcgen05 3xTF32 if available, else FFMA ----------
__global__ void __launch_bounds__(256, 1) k_scan(const float* __restrict__ Wh) {
    extern __shared__ char smem[];
    const int tid = threadIdx.x;
    const int cta = blockIdx.x;      // 0..127
    const int nb = cta & 15;         // N tile (64 cols)
    const int kz = cta >> 4;         // K slice (128 rows)

#if HAS_TCGEN05
    // =========================== tensor-core path ===========================
    const uint32_t smb = smem_u32(smem);
    const int wid = tid >> 5, lid = tid & 31;

    if (tid == 0) {
        MBAR_INIT(smb + SM_CPMBAR, 1);
        MBAR_INIT(smb + SM_MMAMBAR, 1);
    }
    if (wid == 0) TC_ALLOC(smb + SM_TMEMPTR, 64);
    __syncthreads();
    uint32_t tmem;
    asm volatile("ld.shared.b32 %0, [%1];" : "=r"(tmem) : "r"(smb + SM_TMEMPTR));

    // build B tiles: B[n][k] = Wh[kz*128+k][nb*64+n], tf32 hi/lo, blocked SW128
    for (int s = tid; s < 64 * 128; s += 256) {
        int n = s >> 7, k = s & 127;
        float w = Wh[(size_t)(kz * 128 + k) * Hn + nb * 64 + n];
        float hi = tf32_hi_f(w);
        int ac = k >> 5, inner = k & 31;
        uint32_t off = (uint32_t)(ac * 8192 + n * 128 + inner * 4);
        uint32_t sw = off ^ ((off >> 3) & 0x70);
        *(float*)(smem + SM_BHI + sw) = hi;
        *(float*)(smem + SM_BLO + sw) = w - hi;
    }
    {
        int t = cta * 256 + tid;
        ((float4*)g_hi)[t] = make_float4(0.f, 0.f, 0.f, 0.f);
        ((float4*)g_lo)[t] = make_float4(0.f, 0.f, 0.f, 0.f);
    }
    FENCE_ASYNC_SHARED();
    __syncthreads();

    float4 c4s = make_float4(0.f, 0.f, 0.f, 0.f);

    // phase-B hi/lo store addressing (row b = cta, k-range tid*4..+3)
    const int wk0 = tid * 4;
    const int wkz = wk0 >> 7, wac = (wk0 >> 5) & 3, winner = wk0 & 31;
    uint32_t woff = (uint32_t)(cta * 128 + winner * 4);
    woff = woff ^ ((woff >> 3) & 0x70);
    char* whi = (char*)g_hi + (wkz * 4 + wac) * 16384 + woff;
    char* wlo = (char*)g_lo + (wkz * 4 + wac) * 16384 + woff;

    const uint64_t aHd = make_desc(smb + SM_AHI);
    const uint64_t aLd = make_desc(smb + SM_ALO);
    const uint64_t bHd = make_desc(smb + SM_BHI);
    const uint64_t bLd = make_desc(smb + SM_BLO);

    grid_sync();

    for (int l = 0; l < Ln; l++) {
        const unsigned par = l & 1;
        if (tid == 0) {
            MBAR_EXPECT_TX(smb + SM_CPMBAR, 131072u);
            bulk_g2s(smb + SM_AHI, (const char*)g_hi + kz * 65536, 65536u, smb + SM_CPMBAR);
            bulk_g2s(smb + SM_ALO, (const char*)g_lo + kz * 65536, 65536u, smb + SM_CPMBAR);
        }
        if (wid == 0) {
            MBAR_WAIT(smb + SM_CPMBAR, par);
            if (elect_one()) {
                bool first = true;
#pragma unroll
                for (int pass = 0; pass < 3; pass++) {
                    uint64_t ad = (pass == 2) ? aLd : aHd;
                    uint64_t bd = (pass == 1) ? bLd : bHd;
#pragma unroll
                    for (int s = 0; s < 16; s++) {
                        uint64_t ao = (uint64_t)((s >> 2) * 1024 + (s & 3) * 2);
                        uint64_t bo = (uint64_t)((s >> 2) * 512 + (s & 3) * 2);
                        mma_tf32_ss(tmem, ad + ao, bd + bo, IDESC_TF32, !first);
                        first = false;
                    }
                }
                TC_COMMIT(smb + SM_MMAMBAR);
            }
        }
        MBAR_WAIT(smb + SM_MMAMBAR, par);
        TC_FENCE_AFTER();

        {
            uint32_t r[32];
            const int cbase = (wid < 4) ? 0 : 32;
            LDTM_X32(r, tmem + cbase);
            TC_WAIT_LD();
            TC_FENCE_BEFORE();
            const int m = (wid & 3) * 32 + lid;
            float* dst = g_zp[kz] + (size_t)m * Hn + nb * 64 + cbase;
#pragma unroll
            for (int j = 0; j < 8; j++) {
                float4 v;
                v.x = __uint_as_float(r[4 * j + 0]);
                v.y = __uint_as_float(r[4 * j + 1]);
                v.z = __uint_as_float(r[4 * j + 2]);
                v.w = __uint_as_float(r[4 * j + 3]);
                *(float4*)(dst + 4 * j) = v;
            }
        }

        float4 xp4 = __ldcg((const float4*)(g_xp + (size_t)l * BH + (size_t)cta * Hn) + tid);

        grid_sync();

        float4 z4 = __ldcg((const float4*)(g_zp[0] + (size_t)cta * Hn) + tid);
#pragma unroll
        for (int ks = 1; ks < KSPLIT; ks++) {
            float4 t = __ldcg((const float4*)(g_zp[ks] + (size_t)cta * Hn) + tid);
            z4.x += t.x; z4.y += t.y; z4.z += t.z; z4.w += t.w;
        }
        z4.x += xp4.x; z4.y += xp4.y; z4.z += xp4.z; z4.w += xp4.w;

        float4 hn;
        hn.x = act1(z4.x, c4s.x);
        hn.y = act1(z4.y, c4s.y);
        hn.z = act1(z4.z, c4s.z);
        hn.w = act1(z4.w, c4s.w);

        ((float4*)(g_hs + (size_t)l * BH))[cta * 256 + tid] = hn;

        float4 hi4, lo4;
        hi4.x = tf32_hi_f(hn.x); lo4.x = hn.x - hi4.x;
        hi4.y = tf32_hi_f(hn.y); lo4.y = hn.y - hi4.y;
        hi4.z = tf32_hi_f(hn.z); lo4.z = hn.z - hi4.z;
        hi4.w = tf32_hi_f(hn.w); lo4.w = hn.w - hi4.w;
        *(float4*)whi = hi4;
        *(float4*)wlo = lo4;

        grid_sync();
    }

    __syncthreads();
    if (wid == 0) TC_DEALLOC(tmem, 64);

#else
    // ============================ FFMA fallback (R5) ============================
    float (*Whs)[68] = (float(*)[68])smem;                       // 128 x 68 floats
    float (*As)[16][132] = (float(*)[16][132])(smem + 128 * 68 * 4);

    for (int s = tid; s < 128 * 16; s += 256) {
        int r = s >> 4, c4 = s & 15;
        *(float4*)&Whs[r][c4 * 4] =
            *(const float4*)(Wh + (size_t)(kz * 128 + r) * Hn + nb * 64 + c4 * 4);
    }
    ((float4*)g_h[0])[cta * 256 + tid] = make_float4(0.f, 0.f, 0.f, 0.f);
    float4 c4s = make_float4(0.f, 0.f, 0.f, 0.f);

    const int ty = tid >> 4, tx = tid & 15;
    const int m0 = ty * 8, n0 = tx * 4;
    const int srow = tid >> 2, sq = tid & 3;
    const int srow2 = (tid + 256) >> 2, sq2 = (tid + 256) & 3;

    grid_sync();

    for (int l = 0; l < Ln; l++) {
        const float* __restrict__ hsrc = g_h[l & 1];
        unsigned long long acc[8][2];
#pragma unroll
        for (int i = 0; i < 8; i++) { acc[i][0] = 0ULL; acc[i][1] = 0ULL; }

        {
            const int kb = kz * 128;
            float4 v0 = __ldcg((const float4*)(hsrc + srow  * Hn + kb + sq  * 4));
            float4 v1 = __ldcg((const float4*)(hsrc + srow2 * Hn + kb + sq2 * 4));
            As[0][sq * 4 + 0][srow] = v0.x;
            As[0][sq * 4 + 1][srow] = v0.y;
            As[0][sq * 4 + 2][srow] = v0.z;
            As[0][sq * 4 + 3][srow] = v0.w;
            As[0][sq2 * 4 + 0][srow2] = v1.x;
            As[0][sq2 * 4 + 1][srow2] = v1.y;
            As[0][sq2 * 4 + 2][srow2] = v1.z;
            As[0][sq2 * 4 + 3][srow2] = v1.w;
        }
        __syncthreads();

#pragma unroll
        for (int kt = 0; kt < 8; kt++) {
            float4 v0, v1;
            if (kt < 7) {
                const int kb = kz * 128 + (kt + 1) * 16;
                v0 = __ldcg((const float4*)(hsrc + srow  * Hn + kb + sq  * 4));
                v1 = __ldcg((const float4*)(hsrc + srow2 * Hn + kb + sq2 * 4));
            }
            const int buf = kt & 1;
#pragma unroll
            for (int k = 0; k < 16; k++) {
                float a[8];
                *(float4*)&a[0] = *(const float4*)&As[buf][k][m0];
                *(float4*)&a[4] = *(const float4*)&As[buf][k][m0 + 4];
                float4 w = *(const float4*)&Whs[kt * 16 + k][n0];
                unsigned long long b0 = *(const unsigned long long*)&w.x;
                unsigned long long b1 = *(const unsigned long long*)&w.z;
#pragma unroll
                for (int i = 0; i < 8; i++) {
                    unsigned long long a2 = pk2(a[i], a[i]);
                    acc[i][0] = ffma2(a2, b0, acc[i][0]);
                    acc[i][1] = ffma2(a2, b1, acc[i][1]);
                }
            }
            if (kt < 7) {
                const int nbuf = 1 - buf;
                As[nbuf][sq * 4 + 0][srow] = v0.x;
                As[nbuf][sq * 4 + 1][srow] = v0.y;
                As[nbuf][sq * 4 + 2][srow] = v0.z;
                As[nbuf][sq * 4 + 3][srow] = v0.w;
                As[nbuf][sq2 * 4 + 0][srow2] = v1.x;
                As[nbuf][sq2 * 4 + 1][srow2] = v1.y;
                As[nbuf][sq2 * 4 + 2][srow2] = v1.z;
                As[nbuf][sq2 * 4 + 3][srow2] = v1.w;
            }
            __syncthreads();
        }

        {
            float* zp = g_zp[kz];
#pragma unroll
            for (int i = 0; i < 8; i++) {
                float lo0, hi0, lo1, hi1;
                upk2(acc[i][0], lo0, hi0);
                upk2(acc[i][1], lo1, hi1);
                *(float4*)(zp + (size_t)(m0 + i) * Hn + nb * 64 + n0) =
                    make_float4(lo0, hi0, lo1, hi1);
            }
        }

        float4 xp4 = __ldcg((const float4*)(g_xp + (size_t)l * BH + (size_t)cta * Hn) + tid);

        grid_sync();

        float4 z4 = __ldcg((const float4*)(g_zp[0] + (size_t)cta * Hn) + tid);
#pragma unroll
        for (int ks = 1; ks < KSPLIT; ks++) {
            float4 t = __ldcg((const float4*)(g_zp[ks] + (size_t)cta * Hn) + tid);
            z4.x += t.x; z4.y += t.y; z4.z += t.z; z4.w += t.w;
        }
        z4.x += xp4.x; z4.y += xp4.y; z4.z += xp4.z; z4.w += xp4.w;

        float4 hn;
        hn.x = act1(z4.x, c4s.x);
        hn.y = act1(z4.y, c4s.y);
        hn.z = act1(z4.z, c4s.z);
        hn.w = act1(z4.w, c4s.w);

        int i4 = cta * 256 + tid;
        ((float4*)g_h[(l + 1) & 1])[i4] = hn;
        ((float4*)(g_hs + (size_t)l * BH))[i4] = hn;

        grid_sync();
    }
#endif
}

// ---------- output projection + mask ----------
__global__ void __launch_bounds__(256) k_out(const float* __restrict__ Wo,
                                             const float* __restrict__ bo,
                                             const int* __restrict__ slen,
                                             float* __restrict__ out) {
    int gw = (blockIdx.x * 256 + threadIdx.x) >> 5;
    int lane = threadIdx.x & 31;
    int b = gw >> 8;
    int l = gw & 255;
    const float* hrow = g_hs + ((size_t)l * Bn + b) * Hn;

    float a0 = 0.f, a1 = 0.f;
    for (int h0 = lane * 4; h0 < Hn; h0 += 128) {
        float4 v  = *(const float4*)(hrow + h0);
        float4 w0 = *(const float4*)(Wo + 2 * h0);
        float4 w1 = *(const float4*)(Wo + 2 * h0 + 4);
        a0 += v.x * w0.x + v.y * w0.z + v.z * w1.x + v.w * w1.z;
        a1 += v.x * w0.y + v.y * w0.w + v.z * w1.y + v.w * w1.w;
    }
#pragma unroll
    for (int off = 16; off; off >>= 1) {
        a0 += __shfl_xor_sync(0xffffffffu, a0, off);
        a1 += __shfl_xor_sync(0xffffffffu, a1, off);
    }
    if (lane == 0) {
        float o0 = 1.f / (1.f + __expf(-(a0 + bo[0])));
        float o1 = 1.f / (1.f + __expf(-(a1 + bo[1])));
        if (l > slen[b]) { o0 = 0.f; o1 = 1.f; }
        out[2 * gw + 0] = o0;
        out[2 * gw + 1] = o1;
    }
}

extern "C" void kernel_launch(void* const* d_in, const int* in_sizes, int n_in,
                              void* d_out, int out_size) {
    const float* x    = (const float*)d_in[0];
    const int*   slen = (const int*)  d_in[1];
    const float* Wh   = (const float*)d_in[2];
    const float* bh   = (const float*)d_in[3];
    const float* Wx   = (const float*)d_in[4];
    const float* bx   = (const float*)d_in[5];
    const float* Wo   = (const float*)d_in[6];
    const float* bo   = (const float*)d_in[7];
    float* out = (float*)d_out;

    cudaFuncSetAttribute(k_scan, cudaFuncAttributeMaxDynamicSharedMemorySize, SM_TOTAL);
    cudaFuncSetAttribute(k_xp_tc, cudaFuncAttributeMaxDynamicSharedMemorySize, XP_SMEM);

    k_cvt_x<<<256, 256>>>(x);
    k_cvt_w<<<16, 256>>>(Wx);
    k_xp_tc<<<dim3(2, 256), 256, XP_SMEM>>>(x, Wx, bx, bh);
    k_scan<<<NCTA, 256, SM_TOTAL>>>(Wh);
    k_out<<<4096, 256>>>(Wo, bo, slen, out);
}

// round 14
// speedup vs baseline: 1.0548x; 1.0548x over previous
#include <cuda_runtime.h>
#include <cstdint>

#define Bn 128
#define Ln 256
#define Dn 512
#define Hn 1024
#define BH (Bn*Hn)      // 131072
#define KSPLIT 8
#define NCTA 128

// Does this compilation pass allow arch-specific (tcgen05) instructions?
#if defined(__CUDA_ARCH_FEAT_SM103_ALL) || defined(__CUDA_ARCH_FEAT_SM100_ALL) || \
    (defined(__CUDA_ARCH_FAMILY_SPECIFIC__) && (__CUDA_ARCH_FAMILY_SPECIFIC__ == 1000 || __CUDA_ARCH_FAMILY_SPECIFIC__ == 1030))
#define HAS_TCGEN05 1
#else
#define HAS_TCGEN05 0
#endif

// scratch (device globals: no allocations allowed)
__device__ float g_xp[(size_t)Ln*BH];   // (L,B,H) pre-activations x@Wx + bx + bh
__device__ float g_hs[(size_t)Ln*BH];   // hidden states per step (for k_out)
__device__ float g_hi[BH];              // h tf32-hi, MMA-ready swizzled blocked layout
__device__ float g_lo[BH];              // h residual lo, same layout (tc path)
__device__ float g_h[2][BH];            // ping-pong h (ffma fallback path)
__device__ float g_zp[KSPLIT][BH];      // K-split partial sums of h@Wh
__device__ float g_xhi[(size_t)32768*Dn];  // x' tf32-hi blocked [mt][ac][b][k]
__device__ float g_xlo[(size_t)32768*Dn];  // x' residual lo, same layout
__device__ float g_wxhi[(size_t)Dn*Hn];    // Wx^T tf32-hi blocked [nt][ac][n][k]
__device__ float g_wxlo[(size_t)Dn*Hn];    // Wx^T residual lo
__device__ unsigned g_cnt[8][128];      // 8 arrive counters, 512B apart
__device__ unsigned g_phase;            // barrier generation (monotonic)

// ---------- packed f32x2 helpers ----------
__device__ __forceinline__ unsigned long long pk2(float lo, float hi) {
    unsigned long long r;
    asm("mov.b64 %0, {%1,%2};" : "=l"(r) : "f"(lo), "f"(hi));
    return r;
}
__device__ __forceinline__ void upk2(unsigned long long v, float& lo, float& hi) {
    asm("mov.b64 {%0,%1}, %2;" : "=f"(lo), "=f"(hi) : "l"(v));
}
__device__ __forceinline__ unsigned long long ffma2(unsigned long long a,
                                                    unsigned long long b,
                                                    unsigned long long c) {
    unsigned long long d;
    asm("fma.rn.f32x2 %0, %1, %2, %3;" : "=l"(d) : "l"(a), "l"(b), "l"(c));
    return d;
}

// ---------- low-contention grid barrier (replay-safe) ----------
__device__ __forceinline__ void grid_sync() {
    __syncthreads();
    if (threadIdx.x == 0) {
        unsigned ph = *(volatile unsigned*)&g_phase;
        __threadfence();
        atomicAdd(&g_cnt[blockIdx.x & 7][0], 1);
        if (blockIdx.x == 0) {
            unsigned sum;
            do {
                sum = 0;
#pragma unroll
                for (int i = 0; i < 8; i++) sum += *(volatile unsigned*)&g_cnt[i][0];
            } while (sum < NCTA);
#pragma unroll
            for (int i = 0; i < 8; i++) *(volatile unsigned*)&g_cnt[i][0] = 0;
            __threadfence();
            *(volatile unsigned*)&g_phase = ph + 1;
        } else {
            while (*(volatile unsigned*)&g_phase == ph) { __nanosleep(32); }
        }
        __threadfence();
    }
    __syncthreads();
}

// ---------- activation ----------
__device__ __forceinline__ float act1(float z, float& c) {
    float sg = 1.0f / (1.0f + __expf(-z));
    float g = tanhf(z);
    c = sg * (c + g);
    return sg * tanhf(c);
}

__device__ __forceinline__ float tf32_hi_f(float x) {
    float r;
    asm("cvt.rna.tf32.f32 %0, %1;" : "=f"(r) : "f"(x));   // plain PTX, sm_80+
    return r;
}

#if HAS_TCGEN05
// ================= tcgen05 helpers (only in arch-specific pass) =================
__device__ __forceinline__ uint32_t smem_u32(const void* p) {
    uint32_t a;
    asm("{ .reg .u64 t; cvta.to.shared.u64 t, %1; cvt.u32.u64 %0, t; }" : "=r"(a) : "l"(p));
    return a;
}
__device__ __forceinline__ uint32_t elect_one() {
    uint32_t p;
    asm volatile("{ .reg .pred p; elect.sync _|p, 0xFFFFFFFF; selp.b32 %0, 1, 0, p; }" : "=r"(p));
    return p;
}
__device__ __forceinline__ void mma_tf32_ss(uint32_t d_tmem, uint64_t a_desc,
                                            uint64_t b_desc, uint32_t idesc, bool acc) {
    uint32_t en = acc ? 1u : 0u;
    asm volatile(
        "{\n\t.reg .pred p;\n\t"
        "setp.ne.u32 p, %4, 0;\n\t"
        "tcgen05.mma.cta_group::1.kind::tf32 [%0], %1, %2, %3, {%5, %5, %5, %5}, p;\n\t}"
        :: "r"(d_tmem), "l"(a_desc), "l"(b_desc), "r"(idesc), "r"(en), "r"(0u)
        : "memory");
}
__device__ __forceinline__ void bulk_g2s(uint32_t dst, const void* src,
                                         uint32_t bytes, uint32_t mbar) {
    asm volatile(
        "cp.async.bulk.shared::cta.global.mbarrier::complete_tx::bytes [%0], [%1], %2, [%3];"
        :: "r"(dst), "l"(src), "r"(bytes), "r"(mbar) : "memory");
}
#define MBAR_INIT(a, c) asm volatile("mbarrier.init.shared.b64 [%0], %1;" :: "r"(a), "r"(c) : "memory")
#define MBAR_EXPECT_TX(a, b) asm volatile("mbarrier.arrive.expect_tx.shared.b64 _, [%0], %1;" :: "r"(a), "r"(b) : "memory")
#define MBAR_WAIT(a, par) do { \
    asm volatile("{\n\t.reg .pred P1;\n\tWL_%=:\n\t" \
        "mbarrier.try_wait.parity.acquire.cta.shared::cta.b64 P1, [%0], %1, 0x989680;\n\t" \
        "@P1 bra.uni WD_%=;\n\tbra.uni WL_%=;\n\tWD_%=:\n\t}" \
        :: "r"(a), "r"(par) : "memory"); } while (0)
#define TC_ALLOC(sm, n)  asm volatile("tcgen05.alloc.cta_group::1.sync.aligned.shared::cta.b32 [%0], %1;" :: "r"(sm), "r"(n) : "memory")
#define TC_DEALLOC(t, n) asm volatile("tcgen05.dealloc.cta_group::1.sync.aligned.b32 %0, %1;" :: "r"(t), "r"(n))
#define TC_COMMIT(mb)    asm volatile("tcgen05.commit.cta_group::1.mbarrier::arrive::one.shared::cluster.b64 [%0];" :: "r"(mb) : "memory")
#define TC_FENCE_AFTER() asm volatile("tcgen05.fence::after_thread_sync;" ::: "memory")
#define TC_FENCE_BEFORE() asm volatile("tcgen05.fence::before_thread_sync;" ::: "memory")
#define TC_WAIT_LD()     asm volatile("tcgen05.wait::ld.sync.aligned;" ::: "memory")
#define FENCE_ASYNC_SHARED() asm volatile("fence.proxy.async.shared::cta;" ::: "memory")

#define LDTM_X32(r, addr) \
    asm volatile("tcgen05.ld.sync.aligned.32x32b.x32.b32 " \
        "{%0,%1,%2,%3,%4,%5,%6,%7,%8,%9,%10,%11,%12,%13,%14,%15," \
        "%16,%17,%18,%19,%20,%21,%22,%23,%24,%25,%26,%27,%28,%29,%30,%31}, [%32];" \
        : "=r"((r)[0]), "=r"((r)[1]), "=r"((r)[2]), "=r"((r)[3]), \
          "=r"((r)[4]), "=r"((r)[5]), "=r"((r)[6]), "=r"((r)[7]), \
          "=r"((r)[8]), "=r"((r)[9]), "=r"((r)[10]), "=r"((r)[11]), \
          "=r"((r)[12]), "=r"((r)[13]), "=r"((r)[14]), "=r"((r)[15]), \
          "=r"((r)[16]), "=r"((r)[17]), "=r"((r)[18]), "=r"((r)[19]), \
          "=r"((r)[20]), "=r"((r)[21]), "=r"((r)[22]), "=r"((r)[23]), \
          "=r"((r)[24]), "=r"((r)[25]), "=r"((r)[26]), "=r"((r)[27]), \
          "=r"((r)[28]), "=r"((r)[29]), "=r"((r)[30]), "=r"((r)[31]) \
        : "r"(addr))

static __device__ __forceinline__ uint64_t make_desc(uint32_t addr) {
    uint64_t d = ((uint64_t)2 << 61) | ((uint64_t)1 << 46) |
                 ((uint64_t)64 << 32) | ((uint64_t)1 << 16);
    return d | ((uint64_t)(addr >> 4) & 0x3FFF);
}
#define IDESC_TF32 ((1u<<4) | (2u<<7) | (2u<<10) | ((64u/8)<<17) | ((128u/16)<<24))
#endif  // HAS_TCGEN05

// SMEM layout for scan tc path (dynamic)
#define SM_TMEMPTR 0
#define SM_CPMBAR  8
#define SM_MMAMBAR 16
#define SM_AHI     1024
#define SM_ALO     (SM_AHI + 65536)
#define SM_BHI     (SM_ALO + 65536)
#define SM_BLO     (SM_BHI + 32768)
#define SM_TOTAL   (SM_BLO + 32768)       // 197632 bytes

// SMEM layout for xp tc kernel
#define XP_TMEMPTR 0
#define XP_MBA0    8
#define XP_MBA1    16
#define XP_MBB0    24
#define XP_MBB1    32
#define XP_MBB2    40
#define XP_MBM0    48
#define XP_MBM1    56
#define XP_A       1024                    // 2 slots x 65536 (hi at +0, lo at +32768)
#define XP_B       (XP_A + 131072)         // 3 slots x 32768 (hi at +0, lo at +16384)
#define XP_SMEM    (XP_B + 98304)          // 230400 bytes

// ---------- conversion: x -> tf32 hi/lo in MMA-ready blocked layout ----------
// g_xhi byte addr = mt*262144 + (k>>5)*16384 + swz(b*128 + (k&31)*4); mt = l
__global__ void __launch_bounds__(256) k_cvt_x(const float* __restrict__ x) {
#if !HAS_TCGEN05
    return;   // fallback image computes xp directly from x
#else
    const int mt = blockIdx.x;             // = l
    char* dhi = (char*)g_xhi + (size_t)mt * 262144;
    char* dlo = (char*)g_xlo + (size_t)mt * 262144;
    for (int idx = threadIdx.x; idx < 128 * 128; idx += 256) {   // (b, k4)
        int b = idx >> 7, k4 = idx & 127;
        float4 v = *(const float4*)(x + ((size_t)b * Ln + mt) * Dn + k4 * 4);
        float4 hi4, lo4;
        hi4.x = tf32_hi_f(v.x); lo4.x = v.x - hi4.x;
        hi4.y = tf32_hi_f(v.y); lo4.y = v.y - hi4.y;
        hi4.z = tf32_hi_f(v.z); lo4.z = v.z - hi4.z;
        hi4.w = tf32_hi_f(v.w); lo4.w = v.w - hi4.w;
        int k = k4 * 4;
        uint32_t off = (uint32_t)(b * 128 + (k & 31) * 4);
        uint32_t sw = off ^ ((off >> 3) & 0x70);
        uint32_t full = (uint32_t)((k >> 5) * 16384) + sw;
        *(float4*)(dhi + full) = hi4;
        *(float4*)(dlo + full) = lo4;
    }
#endif
}

// ---------- conversion: Wx^T -> tf32 hi/lo blocked [nt][ac][n][k] ----------
// byte addr = nt*131072 + (k>>5)*8192 + swz(n*128 + (k&31)*4)
__global__ void __launch_bounds__(256) k_cvt_w(const float* __restrict__ Wx) {
#if !HAS_TCGEN05
    return;
#else
    const int nt = blockIdx.x;             // 0..15
    char* dhi = (char*)g_wxhi + (size_t)nt * 131072;
    char* dlo = (char*)g_wxlo + (size_t)nt * 131072;
    for (int idx = threadIdx.x; idx < 512 * 16; idx += 256) {    // (k, n4)
        int k = idx >> 4, n4 = idx & 15;
        float4 v = *(const float4*)(Wx + (size_t)k * Hn + nt * 64 + n4 * 4);
        float w[4] = {v.x, v.y, v.z, v.w};
#pragma unroll
        for (int j = 0; j < 4; j++) {
            int n = n4 * 4 + j;
            float hi = tf32_hi_f(w[j]);
            uint32_t off = (uint32_t)(n * 128 + (k & 31) * 4);
            uint32_t sw = off ^ ((off >> 3) & 0x70);
            uint32_t full = (uint32_t)((k >> 5) * 8192) + sw;
            *(float*)(dhi + full) = hi;
            *(float*)(dlo + full) = w[j] - hi;
        }
    }
#endif
}

// ---------- xp GEMM: tcgen05 3xTF32 (feature image) / FFMA tiles (fallback) ----------
// grid (2 n-halves, 256 m-tiles). Feature: D[128m,512n] in TMEM, K=512 streamed.
__global__ void __launch_bounds__(256, 1) k_xp_tc(const float* __restrict__ x,
                                                  const float* __restrict__ Wx,
                                                  const float* __restrict__ bx,
                                                  const float* __restrict__ bh) {
    extern __shared__ char smem[];
    const int tid = threadIdx.x;
#if HAS_TCGEN05
    const uint32_t smb = smem_u32(smem);
    const int wid = tid >> 5, lid = tid & 31;
    const int nh = blockIdx.x;             // 0..1
    const int mt = blockIdx.y;             // 0..255

    if (tid == 0) {
        MBAR_INIT(smb + XP_MBA0, 1);
        MBAR_INIT(smb + XP_MBA1, 1);
        MBAR_INIT(smb + XP_MBB0, 1);
        MBAR_INIT(smb + XP_MBB1, 1);
        MBAR_INIT(smb + XP_MBB2, 1);
        MBAR_INIT(smb + XP_MBM0, 1);
        MBAR_INIT(smb + XP_MBM1, 1);
    }
    if (wid == 0) TC_ALLOC(smb + XP_TMEMPTR, 512);
    __syncthreads();
    uint32_t tmem;
    asm volatile("ld.shared.b32 %0, [%1];" : "=r"(tmem) : "r"(smb + XP_TMEMPTR));

    if (tid == 0) {
        const char* xhi = (const char*)g_xhi + (size_t)mt * 262144;
        const char* xlo = (const char*)g_xlo + (size_t)mt * 262144;
        const char* whi = (const char*)g_wxhi;
        const char* wlo = (const char*)g_wxlo;
        const uint32_t amb[2] = {smb + XP_MBA0, smb + XP_MBA1};
        const uint32_t bmb[3] = {smb + XP_MBB0, smb + XP_MBB1, smb + XP_MBB2};
        const uint32_t mbM[2] = {smb + XP_MBM0, smb + XP_MBM1};

        // prologue: A chunk kc=0 -> slot 0; B for it=0,1 -> slots 0,1
        MBAR_EXPECT_TX(amb[0], 65536u);
        bulk_g2s(smb + XP_A, xhi, 32768u, amb[0]);
        bulk_g2s(smb + XP_A + 32768, xlo, 32768u, amb[0]);
#pragma unroll
        for (int p = 0; p < 2; p++) {      // it=p: kc=0, nt=p
            size_t bsrc = (size_t)(nh * 8 + p) * 131072;   // + kc*16384 (kc=0)
            MBAR_EXPECT_TX(bmb[p], 32768u);
            bulk_g2s(smb + XP_B + p * 32768, whi + bsrc, 16384u, bmb[p]);
            bulk_g2s(smb + XP_B + p * 32768 + 16384, wlo + bsrc, 16384u, bmb[p]);
        }

        for (int it = 0; it < 64; it++) {
            const int kc = it >> 3, nt = it & 7;
            if (nt == 0) MBAR_WAIT(amb[kc & 1], (kc >> 1) & 1);
            MBAR_WAIT(bmb[it % 3], (it / 3) & 1);

            const uint32_t aBase = smb + XP_A + (kc & 1) * 65536;
            const uint32_t bBase = smb + XP_B + (it % 3) * 32768;
#pragma unroll
            for (int pass = 0; pass < 3; pass++) {
                uint64_t ad = make_desc(aBase + ((pass == 2) ? 32768u : 0u));
                uint64_t bd = make_desc(bBase + ((pass == 1) ? 16384u : 0u));
#pragma unroll
                for (int s = 0; s < 8; s++) {
                    uint64_t ao = (uint64_t)((s >> 2) * 1024 + (s & 3) * 2);
                    uint64_t bo = (uint64_t)((s >> 2) * 512 + (s & 3) * 2);
                    // zero-init each nt's accumulator at its FIRST MMA (kc==0)
                    mma_tf32_ss(tmem + nt * 64, ad + ao, bd + bo, IDESC_TF32,
                                !(kc == 0 && pass == 0 && s == 0));
                }
            }
            // commit it -> mbM[it&1]; wait commit it-1 on its own barrier with
            // EXACT per-barrier phase (each barrier completes once per 2 its).
            TC_COMMIT(mbM[it & 1]);
            if (it >= 1) MBAR_WAIT(mbM[(it - 1) & 1], ((it - 1) >> 1) & 1);

            if (it + 2 < 64) {            // load B for it+2 (its old user = it-1, waited)
                const int jt = it + 2;
                const int slot = jt % 3;
                size_t bsrc = (size_t)(nh * 8 + (jt & 7)) * 131072 + (size_t)(jt >> 3) * 16384;
                MBAR_EXPECT_TX(bmb[slot], 32768u);
                bulk_g2s(smb + XP_B + slot * 32768, whi + bsrc, 16384u, bmb[slot]);
                bulk_g2s(smb + XP_B + slot * 32768 + 16384, wlo + bsrc, 16384u, bmb[slot]);
            }
            if (nt == 6 && kc < 7) {      // load A for kc+1 (old user kc-1 long done)
                const int nk = kc + 1;
                MBAR_EXPECT_TX(amb[nk & 1], 65536u);
                bulk_g2s(smb + XP_A + (nk & 1) * 65536, xhi + nk * 32768, 32768u, amb[nk & 1]);
                bulk_g2s(smb + XP_A + (nk & 1) * 65536 + 32768, xlo + nk * 32768, 32768u, amb[nk & 1]);
            }
        }
        MBAR_WAIT(mbM[1], 1);             // commit 63: barrier1 use #31 -> phase parity 1
    }
    __syncthreads();
    TC_FENCE_AFTER();

    // epilogue: read D per n-tile, add bias, store to g_xp
    {
        const int m = (wid & 3) * 32 + lid;
        const int row = blockIdx.y * 128 + m;
        for (int nt = 0; nt < 8; nt++) {
            uint32_t r[32];
            const int cb = (wid < 4) ? 0 : 32;
            LDTM_X32(r, tmem + nt * 64 + cb);
            TC_WAIT_LD();
            const int n0 = (nh * 8 + nt) * 64 + cb;
            float* dst = g_xp + (size_t)row * Hn + n0;
#pragma unroll
            for (int q = 0; q < 8; q++) {
                float4 bxv = *(const float4*)(bx + n0 + 4 * q);
                float4 bhv = *(const float4*)(bh + n0 + 4 * q);
                float4 v;
                v.x = __uint_as_float(r[4 * q + 0]) + bxv.x + bhv.x;
                v.y = __uint_as_float(r[4 * q + 1]) + bxv.y + bhv.y;
                v.z = __uint_as_float(r[4 * q + 2]) + bxv.z + bhv.z;
                v.w = __uint_as_float(r[4 * q + 3]) + bxv.w + bhv.w;
                *(float4*)(dst + 4 * q) = v;
            }
        }
    }
    TC_FENCE_BEFORE();
    __syncthreads();
    if (wid == 0) TC_DEALLOC(tmem, 512);

#else
    // ---------- FFMA fallback: 4 of the old 128x128 tiles per CTA ----------
    float (*As)[132] = (float(*)[132])smem;                 // 16 x 132
    float (*Bs)[128] = (float(*)[128])(smem + 16 * 132 * 4);

    const int ty = tid >> 4, tx = tid & 15;
    const int m0 = ty * 8, n0 = tx * 8;
    const int mb = blockIdx.y;

    for (int nb4 = 0; nb4 < 4; nb4++) {
        const int nb = blockIdx.x * 4 + nb4;
        unsigned long long acc[8][4];
#pragma unroll
        for (int i = 0; i < 8; i++)
#pragma unroll
            for (int j = 0; j < 4; j++) acc[i][j] = 0ULL;

        for (int kt = 0; kt < Dn / 16; kt++) {
            const int kb = kt * 16;
#pragma unroll
            for (int p = 0; p < 2; p++) {
                int s = tid + p * 256;
                int row = s >> 2, kq = s & 3;
                int gm = mb * 128 + row;
                int bidx = gm & 127, lidx = gm >> 7;
                float4 v = *(const float4*)(x + ((size_t)bidx * Ln + lidx) * Dn + kb + kq * 4);
                As[kq * 4 + 0][row] = v.x;
                As[kq * 4 + 1][row] = v.y;
                As[kq * 4 + 2][row] = v.z;
                As[kq * 4 + 3][row] = v.w;
            }
#pragma unroll
            for (int p = 0; p < 2; p++) {
                int s = tid + p * 256;
                int kr = s >> 5, c4 = s & 31;
                *(float4*)&Bs[kr][c4 * 4] =
                    *(const float4*)(Wx + (size_t)(kb + kr) * Hn + nb * 128 + c4 * 4);
            }
            __syncthreads();
#pragma unroll
            for (int k = 0; k < 16; k++) {
                float a[8];
                *(float4*)&a[0] = *(const float4*)&As[k][m0];
                *(float4*)&a[4] = *(const float4*)&As[k][m0 + 4];
                const unsigned long long* bsrc = (const unsigned long long*)&Bs[k][n0];
                unsigned long long b2[4];
#pragma unroll
                for (int j = 0; j < 4; j++) b2[j] = bsrc[j];
#pragma unroll
                for (int i = 0; i < 8; i++) {
                    unsigned long long a2 = pk2(a[i], a[i]);
#pragma unroll
                    for (int j = 0; j < 4; j++) acc[i][j] = ffma2(a2, b2[j], acc[i][j]);
                }
            }
            __syncthreads();
        }

        float bb[8];
#pragma unroll
        for (int j = 0; j < 8; j++) {
            int gn = nb * 128 + n0 + j;
            bb[j] = bx[gn] + bh[gn];
        }
#pragma unroll
        for (int i = 0; i < 8; i++) {
            int gm = mb * 128 + m0 + i;
            float* orow = g_xp + (size_t)gm * Hn + nb * 128 + n0;
#pragma unroll
            for (int j = 0; j < 4; j++) {
                float lo, hi;
                upk2(acc[i][j], lo, hi);
                *(float2*)(orow + 2 * j) = make_float2(lo + bb[2 * j], hi + bb[2 * j + 1]);
            }
        }
        __syncthreads();
    }
#endif
}

// ---------- persistent fused scan: tcgen05 3xTF32 if available, else FFMA ----------
__global__ void __launch_bounds__(256, 1) k_scan(const float* __restrict__ Wh) {
    extern __shared__ char smem[];
    const int tid = threadIdx.x;
    const int cta = blockIdx.x;      // 0..127
    const int nb = cta & 15;         // N tile (64 cols)
    const int kz = cta >> 4;         // K slice (128 rows)

#if HAS_TCGEN05
    // =========================== tensor-core path ===========================
    const uint32_t smb = smem_u32(smem);
    const int wid = tid >> 5, lid = tid & 31;

    if (tid == 0) {
        MBAR_INIT(smb + SM_CPMBAR, 1);
        MBAR_INIT(smb + SM_MMAMBAR, 1);
    }
    if (wid == 0) TC_ALLOC(smb + SM_TMEMPTR, 64);
    __syncthreads();
    uint32_t tmem;
    asm volatile("ld.shared.b32 %0, [%1];" : "=r"(tmem) : "r"(smb + SM_TMEMPTR));

    // build B tiles: B[n][k] = Wh[kz*128+k][nb*64+n], tf32 hi/lo, blocked SW128
    for (int s = tid; s < 64 * 128; s += 256) {
        int n = s >> 7, k = s & 127;
        float w = Wh[(size_t)(kz * 128 + k) * Hn + nb * 64 + n];
        float hi = tf32_hi_f(w);
        int ac = k >> 5, inner = k & 31;
        uint32_t off = (uint32_t)(ac * 8192 + n * 128 + inner * 4);
        uint32_t sw = off ^ ((off >> 3) & 0x70);
        *(float*)(smem + SM_BHI + sw) = hi;
        *(float*)(smem + SM_BLO + sw) = w - hi;
    }
    {
        int t = cta * 256 + tid;
        ((float4*)g_hi)[t] = make_float4(0.f, 0.f, 0.f, 0.f);
        ((float4*)g_lo)[t] = make_float4(0.f, 0.f, 0.f, 0.f);
    }
    FENCE_ASYNC_SHARED();
    __syncthreads();

    float4 c4s = make_float4(0.f, 0.f, 0.f, 0.f);

    // phase-B hi/lo store addressing (row b = cta, k-range tid*4..+3)
    const int wk0 = tid * 4;
    const int wkz = wk0 >> 7, wac = (wk0 >> 5) & 3, winner = wk0 & 31;
    uint32_t woff = (uint32_t)(cta * 128 + winner * 4);
    woff = woff ^ ((woff >> 3) & 0x70);
    char* whi = (char*)g_hi + (wkz * 4 + wac) * 16384 + woff;
    char* wlo = (char*)g_lo + (wkz * 4 + wac) * 16384 + woff;

    const uint64_t aHd = make_desc(smb + SM_AHI);
    const uint64_t aLd = make_desc(smb + SM_ALO);
    const uint64_t bHd = make_desc(smb + SM_BHI);
    const uint64_t bLd = make_desc(smb + SM_BLO);

    grid_sync();

    for (int l = 0; l < Ln; l++) {
        const unsigned par = l & 1;
        if (tid == 0) {
            MBAR_EXPECT_TX(smb + SM_CPMBAR, 131072u);
            bulk_g2s(smb + SM_AHI, (const char*)g_hi + kz * 65536, 65536u, smb + SM_CPMBAR);
            bulk_g2s(smb + SM_ALO, (const char*)g_lo + kz * 65536, 65536u, smb + SM_CPMBAR);
        }
        if (wid == 0) {
            MBAR_WAIT(smb + SM_CPMBAR, par);
            if (elect_one()) {
                bool first = true;
#pragma unroll
                for (int pass = 0; pass < 3; pass++) {
                    uint64_t ad = (pass == 2) ? aLd : aHd;
                    uint64_t bd = (pass == 1) ? bLd : bHd;
#pragma unroll
                    for (int s = 0; s < 16; s++) {
                        uint64_t ao = (uint64_t)((s >> 2) * 1024 + (s & 3) * 2);
                        uint64_t bo = (uint64_t)((s >> 2) * 512 + (s & 3) * 2);
                        mma_tf32_ss(tmem, ad + ao, bd + bo, IDESC_TF32, !first);
                        first = false;
                    }
                }
                TC_COMMIT(smb + SM_MMAMBAR);
            }
        }
        MBAR_WAIT(smb + SM_MMAMBAR, par);
        TC_FENCE_AFTER();

        {
            uint32_t r[32];
            const int cbase = (wid < 4) ? 0 : 32;
            LDTM_X32(r, tmem + cbase);
            TC_WAIT_LD();
            TC_FENCE_BEFORE();
            const int m = (wid & 3) * 32 + lid;
            float* dst = g_zp[kz] + (size_t)m * Hn + nb * 64 + cbase;
#pragma unroll
            for (int j = 0; j < 8; j++) {
                float4 v;
                v.x = __uint_as_float(r[4 * j + 0]);
                v.y = __uint_as_float(r[4 * j + 1]);
                v.z = __uint_as_float(r[4 * j + 2]);
                v.w = __uint_as_float(r[4 * j + 3]);
                *(float4*)(dst + 4 * j) = v;
            }
        }

        float4 xp4 = __ldcg((const float4*)(g_xp + (size_t)l * BH + (size_t)cta * Hn) + tid);

        grid_sync();

        float4 z4 = __ldcg((const float4*)(g_zp[0] + (size_t)cta * Hn) + tid);
#pragma unroll
        for (int ks = 1; ks < KSPLIT; ks++) {
            float4 t = __ldcg((const float4*)(g_zp[ks] + (size_t)cta * Hn) + tid);
            z4.x += t.x; z4.y += t.y; z4.z += t.z; z4.w += t.w;
        }
        z4.x += xp4.x; z4.y += xp4.y; z4.z += xp4.z; z4.w += xp4.w;

        float4 hn;
        hn.x = act1(z4.x, c4s.x);
        hn.y = act1(z4.y, c4s.y);
        hn.z = act1(z4.z, c4s.z);
        hn.w = act1(z4.w, c4s.w);

        ((float4*)(g_hs + (size_t)l * BH))[cta * 256 + tid] = hn;

        float4 hi4, lo4;
        hi4.x = tf32_hi_f(hn.x); lo4.x = hn.x - hi4.x;
        hi4.y = tf32_hi_f(hn.y); lo4.y = hn.y - hi4.y;
        hi4.z = tf32_hi_f(hn.z); lo4.z = hn.z - hi4.z;
        hi4.w = tf32_hi_f(hn.w); lo4.w = hn.w - hi4.w;
        *(float4*)whi = hi4;
        *(float4*)wlo = lo4;

        grid_sync();
    }

    __syncthreads();
    if (wid == 0) TC_DEALLOC(tmem, 64);

#else
    // ============================ FFMA fallback (R5) ============================
    float (*Whs)[68] = (float(*)[68])smem;                       // 128 x 68 floats
    float (*As)[16][132] = (float(*)[16][132])(smem + 128 * 68 * 4);

    for (int s = tid; s < 128 * 16; s += 256) {
        int r = s >> 4, c4 = s & 15;
        *(float4*)&Whs[r][c4 * 4] =
            *(const float4*)(Wh + (size_t)(kz * 128 + r) * Hn + nb * 64 + c4 * 4);
    }
    ((float4*)g_h[0])[cta * 256 + tid] = make_float4(0.f, 0.f, 0.f, 0.f);
    float4 c4s = make_float4(0.f, 0.f, 0.f, 0.f);

    const int ty = tid >> 4, tx = tid & 15;
    const int m0 = ty * 8, n0 = tx * 4;
    const int srow = tid >> 2, sq = tid & 3;
    const int srow2 = (tid + 256) >> 2, sq2 = (tid + 256) & 3;

    grid_sync();

    for (int l = 0; l < Ln; l++) {
        const float* __restrict__ hsrc = g_h[l & 1];
        unsigned long long acc[8][2];
#pragma unroll
        for (int i = 0; i < 8; i++) { acc[i][0] = 0ULL; acc[i][1] = 0ULL; }

        {
            const int kb = kz * 128;
            float4 v0 = __ldcg((const float4*)(hsrc + srow  * Hn + kb + sq  * 4));
            float4 v1 = __ldcg((const float4*)(hsrc + srow2 * Hn + kb + sq2 * 4));
            As[0][sq * 4 + 0][srow] = v0.x;
            As[0][sq * 4 + 1][srow] = v0.y;
            As[0][sq * 4 + 2][srow] = v0.z;
            As[0][sq * 4 + 3][srow] = v0.w;
            As[0][sq2 * 4 + 0][srow2] = v1.x;
            As[0][sq2 * 4 + 1][srow2] = v1.y;
            As[0][sq2 * 4 + 2][srow2] = v1.z;
            As[0][sq2 * 4 + 3][srow2] = v1.w;
        }
        __syncthreads();

#pragma unroll
        for (int kt = 0; kt < 8; kt++) {
            float4 v0, v1;
            if (kt < 7) {
                const int kb = kz * 128 + (kt + 1) * 16;
                v0 = __ldcg((const float4*)(hsrc + srow  * Hn + kb + sq  * 4));
                v1 = __ldcg((const float4*)(hsrc + srow2 * Hn + kb + sq2 * 4));
            }
            const int buf = kt & 1;
#pragma unroll
            for (int k = 0; k < 16; k++) {
                float a[8];
                *(float4*)&a[0] = *(const float4*)&As[buf][k][m0];
                *(float4*)&a[4] = *(const float4*)&As[buf][k][m0 + 4];
                float4 w = *(const float4*)&Whs[kt * 16 + k][n0];
                unsigned long long b0 = *(const unsigned long long*)&w.x;
                unsigned long long b1 = *(const unsigned long long*)&w.z;
#pragma unroll
                for (int i = 0; i < 8; i++) {
                    unsigned long long a2 = pk2(a[i], a[i]);
                    acc[i][0] = ffma2(a2, b0, acc[i][0]);
                    acc[i][1] = ffma2(a2, b1, acc[i][1]);
                }
            }
            if (kt < 7) {
                const int nbuf = 1 - buf;
                As[nbuf][sq * 4 + 0][srow] = v0.x;
                As[nbuf][sq * 4 + 1][srow] = v0.y;
                As[nbuf][sq * 4 + 2][srow] = v0.z;
                As[nbuf][sq * 4 + 3][srow] = v0.w;
                As[nbuf][sq2 * 4 + 0][srow2] = v1.x;
                As[nbuf][sq2 * 4 + 1][srow2] = v1.y;
                As[nbuf][sq2 * 4 + 2][srow2] = v1.z;
                As[nbuf][sq2 * 4 + 3][srow2] = v1.w;
            }
            __syncthreads();
        }

        {
            float* zp = g_zp[kz];
#pragma unroll
            for (int i = 0; i < 8; i++) {
                float lo0, hi0, lo1, hi1;
                upk2(acc[i][0], lo0, hi0);
                upk2(acc[i][1], lo1, hi1);
                *(float4*)(zp + (size_t)(m0 + i) * Hn + nb * 64 + n0) =
                    make_float4(lo0, hi0, lo1, hi1);
            }
        }

        float4 xp4 = __ldcg((const float4*)(g_xp + (size_t)l * BH + (size_t)cta * Hn) + tid);

        grid_sync();

        float4 z4 = __ldcg((const float4*)(g_zp[0] + (size_t)cta * Hn) + tid);
#pragma unroll
        for (int ks = 1; ks < KSPLIT; ks++) {
            float4 t = __ldcg((const float4*)(g_zp[ks] + (size_t)cta * Hn) + tid);
            z4.x += t.x; z4.y += t.y; z4.z += t.z; z4.w += t.w;
        }
        z4.x += xp4.x; z4.y += xp4.y; z4.z += xp4.z; z4.w += xp4.w;

        float4 hn;
        hn.x = act1(z4.x, c4s.x);
        hn.y = act1(z4.y, c4s.y);
        hn.z = act1(z4.z, c4s.z);
        hn.w = act1(z4.w, c4s.w);

        int i4 = cta * 256 + tid;
        ((float4*)g_h[(l + 1) & 1])[i4] = hn;
        ((float4*)(g_hs + (size_t)l * BH))[i4] = hn;

        grid_sync();
    }
#endif
}

// ---------- output projection + mask ----------
__global__ void __launch_bounds__(256) k_out(const float* __restrict__ Wo,
                                             const float* __restrict__ bo,
                                             const int* __restrict__ slen,
                                             float* __restrict__ out) {
    int gw = (blockIdx.x * 256 + threadIdx.x) >> 5;
    int lane = threadIdx.x & 31;
    int b = gw >> 8;
    int l = gw & 255;
    const float* hrow = g_hs + ((size_t)l * Bn + b) * Hn;

    float a0 = 0.f, a1 = 0.f;
    for (int h0 = lane * 4; h0 < Hn; h0 += 128) {
        float4 v  = *(const float4*)(hrow + h0);
        float4 w0 = *(const float4*)(Wo + 2 * h0);
        float4 w1 = *(const float4*)(Wo + 2 * h0 + 4);
        a0 += v.x * w0.x + v.y * w0.z + v.z * w1.x + v.w * w1.z;
        a1 += v.x * w0.y + v.y * w0.w + v.z * w1.y + v.w * w1.w;
    }
#pragma unroll
    for (int off = 16; off; off >>= 1) {
        a0 += __shfl_xor_sync(0xffffffffu, a0, off);
        a1 += __shfl_xor_sync(0xffffffffu, a1, off);
    }
    if (lane == 0) {
        float o0 = 1.f / (1.f + __expf(-(a0 + bo[0])));
        float o1 = 1.f / (1.f + __expf(-(a1 + bo[1])));
        if (l > slen[b]) { o0 = 0.f; o1 = 1.f; }
        out[2 * gw + 0] = o0;
        out[2 * gw + 1] = o1;
    }
}

extern "C" void kernel_launch(void* const* d_in, const int* in_sizes, int n_in,
                              void* d_out, int out_size) {
    const float* x    = (const float*)d_in[0];
    const int*   slen = (const int*)  d_in[1];
    const float* Wh   = (const float*)d_in[2];
    const float* bh   = (const float*)d_in[3];
    const float* Wx   = (const float*)d_in[4];
    const float* bx   = (const float*)d_in[5];
    const float* Wo   = (const float*)d_in[6];
    const float* bo   = (const float*)d_in[7];
    float* out = (float*)d_out;

    cudaFuncSetAttribute(k_scan, cudaFuncAttributeMaxDynamicSharedMemorySize, SM_TOTAL);
    cudaFuncSetAttribute(k_xp_tc, cudaFuncAttributeMaxDynamicSharedMemorySize, XP_SMEM);

    k_cvt_x<<<256, 256>>>(x);
    k_cvt_w<<<16, 256>>>(Wx);
    k_xp_tc<<<dim3(2, 256), 256, XP_SMEM>>>(x, Wx, bx, bh);
    k_scan<<<NCTA, 256, SM_TOTAL>>>(Wh);
    k_out<<<4096, 256>>>(Wo, bo, slen, out);
}